// round 12
// baseline (speedup 1.0000x reference)
#include <cuda_runtime.h>

#define BB 128
#define PP 4096
#define NN 64

// One fused kernel. Block = (batch b, center-octet g): 256 threads = 8 warps.
// Each warp sweeps its own 512-point range for the SAME 8 centers
// (coeffs register-resident), 4 points/lane/iter -> 32 independent EX2
// chains per warp per iteration. grid = 1024; __launch_bounds__(256,2)
// -> 128-reg budget: ptxas can keep all chains + loads in flight.
// q[n](x) = K + a0*x0^2 + b0*x0 + a1*x1^2 + b1*x1,  exp(-dist) = EX2(q)
// Uniform fast path (all 8 centers share a0,a1):
//   q = (K_n + B0_n*x0 + B1_n*x1) + base(x),  base = a0*x0^2 + a1*x1^2
__global__ __launch_bounds__(256, 2) void slayer_fused(
    const float4* __restrict__ batch,    // [B, P/2] of float4 (2 points, D=2)
    const float2* __restrict__ mask,     // [B, P/2] of float2
    const float*  __restrict__ centers,  // [N, D]
    const float*  __restrict__ sharp,    // [N, D]
    float*        __restrict__ out)      // [B, N]
{
    const int b    = blockIdx.x >> 3;
    const int g    = blockIdx.x & 7;     // centers [8g, 8g+8)
    const int tid  = threadIdx.x;
    const int warp = tid >> 5;
    const int lane = tid & 31;
    const int n0   = 8 * g;

    __shared__ float partial[8][8];      // [warp][center]

    const float L = 1.4426950408889634f;  // log2(e)

    // Linear coefficients for 8 centers; uniformity check on a0/a1.
    float B0[8], B1[8], KK[8], acc[8];
    float a00 = 0.0f, a10 = 0.0f;
    bool uniform = true;
#pragma unroll
    for (int j = 0; j < 8; j++) {
        const int n = n0 + j;
        const float c0 = __ldg(centers + 2 * n);
        const float c1 = __ldg(centers + 2 * n + 1);
        const float s0 = __ldg(sharp + 2 * n);
        const float s1 = __ldg(sharp + 2 * n + 1);
        const float a0 = -L * s0 * s0;
        const float a1 = -L * s1 * s1;
        if (j == 0) { a00 = a0; a10 = a1; }
        uniform = uniform && (a0 == a00) && (a1 == a10);
        B0[j] = -2.0f * a0 * c0;
        B1[j] = -2.0f * a1 * c1;
        KK[j] = a0 * c0 * c0 + a1 * c1 * c1;
        acc[j] = 0.0f;
    }

    // This warp's 512-point range: 256 float4 entries, consumed 2 per iter.
    const float4* bp = batch + (size_t)b * (PP / 2) + warp * 256 + lane;
    const float2* mp = mask  + (size_t)b * (PP / 2) + warp * 256 + lane;

    constexpr int ITERS = 4;   // 4 iters x 32 lanes x 4 points = 512 points

    if (uniform) {
#pragma unroll
        for (int it = 0; it < ITERS; it++) {
            // Two float4 loads = 4 points: A,B from x; C,D from y.
            const float4 x = __ldg(bp + it * 64);
            const float4 y = __ldg(bp + it * 64 + 32);
            const float2 mx = __ldg(mp + it * 64);
            const float2 my = __ldg(mp + it * 64 + 32);

            const float basea = fmaf(a00 * x.x, x.x, (a10 * x.y) * x.y);
            const float baseb = fmaf(a00 * x.z, x.z, (a10 * x.w) * x.w);
            const float basec = fmaf(a00 * y.x, y.x, (a10 * y.y) * y.y);
            const float based = fmaf(a00 * y.z, y.z, (a10 * y.w) * y.w);

#pragma unroll
            for (int j = 0; j < 8; j++) {
                float qa = fmaf(B0[j], x.x, KK[j]);
                qa = fmaf(B1[j], x.y, qa);
                qa += basea;
                float qb = fmaf(B0[j], x.z, KK[j]);
                qb = fmaf(B1[j], x.w, qb);
                qb += baseb;
                float qc = fmaf(B0[j], y.x, KK[j]);
                qc = fmaf(B1[j], y.y, qc);
                qc += basec;
                float qd = fmaf(B0[j], y.z, KK[j]);
                qd = fmaf(B1[j], y.w, qd);
                qd += based;
                float ea, eb, ec, ed;
                asm("ex2.approx.ftz.f32 %0, %1;" : "=f"(ea) : "f"(qa));
                asm("ex2.approx.ftz.f32 %0, %1;" : "=f"(eb) : "f"(qb));
                asm("ex2.approx.ftz.f32 %0, %1;" : "=f"(ec) : "f"(qc));
                asm("ex2.approx.ftz.f32 %0, %1;" : "=f"(ed) : "f"(qd));
                acc[j] = fmaf(mx.x, ea, acc[j]);
                acc[j] = fmaf(mx.y, eb, acc[j]);
                acc[j] = fmaf(my.x, ec, acc[j]);
                acc[j] = fmaf(my.y, ed, acc[j]);
            }
        }

        // Reduce over lanes, stash per-warp partials
#pragma unroll
        for (int off = 16; off > 0; off >>= 1) {
#pragma unroll
            for (int j = 0; j < 8; j++)
                acc[j] += __shfl_xor_sync(0xffffffffu, acc[j], off);
        }
        if (lane == 0) {
#pragma unroll
            for (int j = 0; j < 8; j++)
                partial[warp][j] = acc[j];
        }
    } else {
        // General path (cold): full quadratic, 2 passes of 4 centers,
        // 2 points per iteration.
        for (int pass = 0; pass < 2; pass++) {
            float A0g[4], B0g[4], A1g[4], B1g[4], Kg[4], ac[4];
#pragma unroll
            for (int j = 0; j < 4; j++) {
                const int n = n0 + 4 * pass + j;
                const float c0 = __ldg(centers + 2 * n);
                const float c1 = __ldg(centers + 2 * n + 1);
                const float s0 = __ldg(sharp + 2 * n);
                const float s1 = __ldg(sharp + 2 * n + 1);
                const float a0 = -L * s0 * s0;
                const float a1 = -L * s1 * s1;
                A0g[j] = a0;
                A1g[j] = a1;
                B0g[j] = -2.0f * a0 * c0;
                B1g[j] = -2.0f * a1 * c1;
                Kg[j]  = a0 * c0 * c0 + a1 * c1 * c1;
                ac[j]  = 0.0f;
            }
#pragma unroll 2
            for (int it = 0; it < 8; it++) {
                const float4 x = __ldg(bp + it * 32);
                const float2 m = __ldg(mp + it * 32);
                const float xa0 = x.x * x.x, xa1 = x.y * x.y;
                const float xb0 = x.z * x.z, xb1 = x.w * x.w;
#pragma unroll
                for (int j = 0; j < 4; j++) {
                    float qa = Kg[j];
                    qa = fmaf(A0g[j], xa0, qa);
                    qa = fmaf(B0g[j], x.x, qa);
                    qa = fmaf(A1g[j], xa1, qa);
                    qa = fmaf(B1g[j], x.y, qa);
                    float qb = Kg[j];
                    qb = fmaf(A0g[j], xb0, qb);
                    qb = fmaf(B0g[j], x.z, qb);
                    qb = fmaf(A1g[j], xb1, qb);
                    qb = fmaf(B1g[j], x.w, qb);
                    float ea, eb;
                    asm("ex2.approx.ftz.f32 %0, %1;" : "=f"(ea) : "f"(qa));
                    asm("ex2.approx.ftz.f32 %0, %1;" : "=f"(eb) : "f"(qb));
                    ac[j] = fmaf(m.x, ea, ac[j]);
                    ac[j] = fmaf(m.y, eb, ac[j]);
                }
            }
#pragma unroll
            for (int off = 16; off > 0; off >>= 1) {
#pragma unroll
                for (int j = 0; j < 4; j++)
                    ac[j] += __shfl_xor_sync(0xffffffffu, ac[j], off);
            }
            if (lane == 0) {
#pragma unroll
                for (int j = 0; j < 4; j++)
                    partial[warp][4 * pass + j] = ac[j];
            }
        }
    }

    __syncthreads();

    // Combine 8 warp partials -> 8 outputs for this block
    if (tid < 8) {
        float v = 0.0f;
#pragma unroll
        for (int w = 0; w < 8; w++)
            v += partial[w][tid];
        out[b * NN + n0 + tid] = v;
    }
}

extern "C" void kernel_launch(void* const* d_in, const int* in_sizes, int n_in,
                              void* d_out, int out_size) {
    const float* batch   = (const float*)d_in[0];   // [B,P,D] f32
    const float* mask    = (const float*)d_in[1];   // [B,P]   f32
    const float* centers = (const float*)d_in[2];   // [N,D]   f32
    const float* sharp   = (const float*)d_in[3];   // [N,D]   f32
    float* out = (float*)d_out;                     // [B,N]   f32

    slayer_fused<<<BB * 8, 256>>>((const float4*)batch, (const float2*)mask,
                                  centers, sharp, out);
}